// round 1
// baseline (speedup 1.0000x reference)
#include <cuda_runtime.h>
#include <math.h>

// Problem constants (fixed by setup_inputs)
#define BATCH 128
#define PP 1024
#define LP 128
#define H 256
#define NP (BATCH*PP)
#define NL (BATCH*LP)

// Scratch (device globals: no allocation allowed)
__device__ float g_Telem[128*H];   // E_elem @ Wd1
__device__ float g_Tab[64*H];      // (E_aa + E_bb) @ Wd1 + bd1, indexed by a*2+bb
__device__ float g_Tlig[16*H];     // E_lig @ Wd1 + bd1
__device__ float g_pool_p[BATCH*H];
__device__ float g_pool_l[BATCH*H];
__device__ float g_contact[BATCH*2];

__device__ __forceinline__ float silu_f(float x) {
    float ax = fabsf(x);
    if (ax < 0.25f) {
        // sigmoid(x) = 1/2 + x/4 - x^3/48 + x^5/480 ; trunc err < 2e-8 at |x|=0.25
        float x2 = x * x;
        float s = 0.5f + x * (0.25f + x2 * (-2.0833333e-2f + x2 * 2.0833333e-3f));
        return x * s;
    }
    return x / (1.0f + expf(-x));
}

// ---------------------------------------------------------------------------
// Kernel A: precompute tables (blocks 0..207) + zero pool accumulators (208..239)
// grid = 240 blocks x 256 threads
// ---------------------------------------------------------------------------
__global__ void prep_kernel(const float* __restrict__ E_elem,
                            const float* __restrict__ E_aa,
                            const float* __restrict__ E_bb,
                            const float* __restrict__ E_lig,
                            const float* __restrict__ Wd1,
                            const float* __restrict__ bd1) {
    int blk = blockIdx.x;
    int h = threadIdx.x;           // 0..255
    if (blk >= 208) {              // zero pools: 32 blocks * 2048 floats = 65536
        int base = (blk - 208) * 2048;
        #pragma unroll
        for (int r = 0; r < 8; r++) {
            int idx = base + r * 256 + h;
            if (idx < BATCH*H) g_pool_p[idx] = 0.0f;
            else               g_pool_l[idx - BATCH*H] = 0.0f;
        }
        return;
    }
    __shared__ float srow[H];
    float bias = 0.0f;
    float* dst;
    if (blk < 128) {
        srow[h] = E_elem[blk*H + h];
        dst = g_Telem + blk*H;
    } else if (blk < 192) {
        int r = blk - 128;
        int a = r >> 1, bb = r & 1;
        srow[h] = E_aa[a*H + h] + E_bb[bb*H + h];
        bias = bd1[h];
        dst = g_Tab + r*H;
    } else {
        int t = blk - 192;
        srow[h] = E_lig[t*H + h];
        bias = bd1[h];
        dst = g_Tlig + t*H;
    }
    __syncthreads();
    float acc = bias;
    #pragma unroll 8
    for (int k = 0; k < H; k++)
        acc = fmaf(srow[k], Wd1[k*H + h], acc);
    dst[h] = acc;
}

// ---------------------------------------------------------------------------
// Kernel B: per-node silu + pooled accumulation.
// grid = dim3(BATCH, 5): y=0..3 -> protein chunks of 256 nodes, y=4 -> ligand (128 nodes)
// block = 256 threads: tid = slot*64 + fg ; fg handles features [4fg, 4fg+4)
// ---------------------------------------------------------------------------
__global__ void node_kernel(const int* __restrict__ elem,
                            const int* __restrict__ aa,
                            const int* __restrict__ bbone,
                            const int* __restrict__ ltype) {
    int b  = blockIdx.x;
    int cy = blockIdx.y;
    int tid  = threadIdx.x;
    int fg   = tid & 63;
    int slot = tid >> 6;

    __shared__ int sh_e[256];
    __shared__ int sh_ab[256];
    __shared__ float4 sh_acc[256];

    float4 acc = make_float4(0.f, 0.f, 0.f, 0.f);

    if (cy < 4) {
        int base = b*PP + cy*256;
        sh_e[tid]  = elem[base + tid];
        sh_ab[tid] = aa[base + tid]*2 + bbone[base + tid];
        __syncthreads();
        const float4* Te = reinterpret_cast<const float4*>(g_Telem);
        const float4* Ta = reinterpret_cast<const float4*>(g_Tab);
        #pragma unroll 4
        for (int j = slot; j < 256; j += 4) {
            int e  = sh_e[j];
            int ab = sh_ab[j];
            float4 u = Te[e*64 + fg];
            float4 v = Ta[ab*64 + fg];
            acc.x += silu_f(u.x + v.x);
            acc.y += silu_f(u.y + v.y);
            acc.z += silu_f(u.z + v.z);
            acc.w += silu_f(u.w + v.w);
        }
    } else {
        int base = b*LP;
        if (tid < 128) sh_e[tid] = ltype[base + tid];
        __syncthreads();
        const float4* Tl = reinterpret_cast<const float4*>(g_Tlig);
        #pragma unroll 4
        for (int j = slot; j < 128; j += 4) {
            float4 u = Tl[sh_e[j]*64 + fg];
            acc.x += silu_f(u.x);
            acc.y += silu_f(u.y);
            acc.z += silu_f(u.z);
            acc.w += silu_f(u.w);
        }
    }

    sh_acc[tid] = acc;   // tid == slot*64+fg
    __syncthreads();
    if (slot == 0) {
        float4 s0 = sh_acc[fg];
        float4 s1 = sh_acc[64 + fg];
        float4 s2 = sh_acc[128 + fg];
        float4 s3 = sh_acc[192 + fg];
        float4 s;
        s.x = (s0.x + s1.x) + (s2.x + s3.x);
        s.y = (s0.y + s1.y) + (s2.y + s3.y);
        s.z = (s0.z + s1.z) + (s2.z + s3.z);
        s.w = (s0.w + s1.w) + (s2.w + s3.w);
        float* dst = (cy < 4 ? g_pool_p : g_pool_l) + b*H + fg*4;
        atomicAdd(dst + 0, s.x);
        atomicAdd(dst + 1, s.y);
        atomicAdd(dst + 2, s.z);
        atomicAdd(dst + 3, s.w);
    }
}

// ---------------------------------------------------------------------------
// Kernel C: per-batch ligand->protein min distance, contact features.
// grid = BATCH blocks x 256 threads. Thread = (ligand atom, protein half).
// min(sqrt(d2)) = sqrt(min(d2)); one sqrt per ligand atom.
// ---------------------------------------------------------------------------
__global__ void dist_kernel(const float* __restrict__ ppos,
                            const float* __restrict__ lpos) {
    int b = blockIdx.x;
    int tid = threadIdx.x;
    __shared__ float4 sh_p[PP];
    __shared__ float sh_m[256];

    const float* pb = ppos + (size_t)b * PP * 3;
    float* shpf = reinterpret_cast<float*>(sh_p);
    for (int i = tid; i < PP*3; i += 256) {
        int j = i / 3, c = i - j*3;
        shpf[j*4 + c] = pb[i];
    }
    __syncthreads();

    int la   = tid & 127;
    int half = tid >> 7;
    const float* lp = lpos + ((size_t)b*LP + la) * 3;
    float lx = lp[0], ly = lp[1], lz = lp[2];
    float m = 3.4e38f;
    int j0 = half * 512;
    #pragma unroll 4
    for (int j = j0; j < j0 + 512; j++) {
        float4 p = sh_p[j];
        float dx = lx - p.x, dy = ly - p.y, dz = lz - p.z;
        float d2 = fmaf(dx, dx, fmaf(dy, dy, dz*dz));
        m = fminf(m, d2);
    }
    sh_m[tid] = m;
    __syncthreads();
    if (tid < 128) {
        float d = sqrtf(fminf(sh_m[tid], sh_m[tid + 128]));
        sh_m[tid] = d;
    }
    __syncthreads();
    if (tid < 32) {
        float s = 0.0f, mn = 3.4e38f;
        #pragma unroll
        for (int k = tid; k < 128; k += 32) {
            s += sh_m[k];
            mn = fminf(mn, sh_m[k]);
        }
        #pragma unroll
        for (int o = 16; o > 0; o >>= 1) {
            s += __shfl_xor_sync(0xffffffffu, s, o);
            mn = fminf(mn, __shfl_xor_sync(0xffffffffu, mn, o));
        }
        if (tid == 0) {
            g_contact[b*2 + 0] = s * (1.0f / 128.0f);
            g_contact[b*2 + 1] = mn;
        }
    }
}

// ---------------------------------------------------------------------------
// Kernel D: pooled @ Wd2 + bd2, then the affinity head. One batch per block.
// grid = BATCH blocks x 256 threads (thread = feature h).
// ---------------------------------------------------------------------------
__global__ void final_kernel(const float* __restrict__ Wd2,
                             const float* __restrict__ bd2,
                             const float* __restrict__ Wa1,
                             const float* __restrict__ ba1,
                             const float* __restrict__ Wa2,
                             const float* __restrict__ ba2,
                             float* __restrict__ out) {
    int b = blockIdx.x;
    int h = threadIdx.x;
    __shared__ float sh_mp[H], sh_ml[H], sh_gp[H], sh_gl[H], sh_r[H];

    sh_mp[h] = g_pool_p[b*H + h] * (1.0f / (float)PP);
    sh_ml[h] = g_pool_l[b*H + h] * (1.0f / (float)LP);
    __syncthreads();

    float ap = bd2[h], al = bd2[h];
    #pragma unroll 4
    for (int k = 0; k < H; k++) {
        float w = Wd2[k*H + h];
        ap = fmaf(sh_mp[k], w, ap);
        al = fmaf(sh_ml[k], w, al);
    }
    sh_gp[h] = ap;
    sh_gl[h] = al;
    __syncthreads();

    float c0 = g_contact[b*2], c1 = g_contact[b*2 + 1];
    float t = ba1[h] + c0 * Wa1[512*H + h] + c1 * Wa1[513*H + h];
    #pragma unroll 4
    for (int k = 0; k < H; k++) {
        t = fmaf(sh_gp[k], Wa1[k*H + h], t);
        t = fmaf(sh_gl[k], Wa1[(H + k)*H + h], t);
    }
    float hv = silu_f(t) * Wa2[h];

    sh_r[h] = hv;
    __syncthreads();
    for (int off = 128; off > 0; off >>= 1) {
        if (h < off) sh_r[h] += sh_r[h + off];
        __syncthreads();
    }
    if (h == 0) out[b] = sh_r[0] + ba2[0];
}

// ---------------------------------------------------------------------------
extern "C" void kernel_launch(void* const* d_in, const int* in_sizes, int n_in,
                              void* d_out, int out_size) {
    const float* protein_pos = (const float*)d_in[0];
    const float* ligand_pos  = (const float*)d_in[1];
    const int*   p_elem      = (const int*)d_in[2];
    const int*   p_aa        = (const int*)d_in[3];
    const int*   p_bb        = (const int*)d_in[4];
    const int*   l_type      = (const int*)d_in[5];
    // d_in[6] protein_batch, d_in[7] ligand_batch: contiguous repeat(arange(B)) -> implicit
    const float* E_elem = (const float*)d_in[8];
    const float* E_aa   = (const float*)d_in[9];
    const float* E_bb   = (const float*)d_in[10];
    const float* E_lig  = (const float*)d_in[11];
    const float* Wd1    = (const float*)d_in[12];
    const float* bd1    = (const float*)d_in[13];
    const float* Wd2    = (const float*)d_in[14];
    const float* bd2    = (const float*)d_in[15];
    const float* Wa1    = (const float*)d_in[16];
    const float* ba1    = (const float*)d_in[17];
    const float* Wa2    = (const float*)d_in[18];
    const float* ba2    = (const float*)d_in[19];
    float* out = (float*)d_out;

    prep_kernel<<<240, 256>>>(E_elem, E_aa, E_bb, E_lig, Wd1, bd1);
    dist_kernel<<<BATCH, 256>>>(protein_pos, ligand_pos);
    node_kernel<<<dim3(BATCH, 5), 256>>>(p_elem, p_aa, p_bb, l_type);
    final_kernel<<<BATCH, 256>>>(Wd2, bd2, Wa1, ba1, Wa2, ba2, out);
}

// round 3
// speedup vs baseline: 1.1008x; 1.1008x over previous
#include <cuda_runtime.h>
#include <math.h>

// Problem constants (fixed by setup_inputs)
#define BATCH 128
#define PP 1024
#define LP 128
#define H 256
#define NP (BATCH*PP)
#define NL (BATCH*LP)

// Scratch (device globals: no allocation allowed)
__device__ float g_Telem[128*H];   // E_elem @ Wd1
__device__ float g_Tab[64*H];      // (E_aa + E_bb) @ Wd1 + bd1, indexed by a*2+bb
__device__ float g_Tlig[16*H];     // E_lig @ Wd1 + bd1
__device__ float g_pool_p[BATCH*H];
__device__ float g_pool_l[BATCH*H];
__device__ float g_contact[BATCH*2];

__device__ __forceinline__ float silu_f(float x) {
    float ax = fabsf(x);
    if (ax < 0.25f) {
        // sigmoid(x) = 1/2 + x/4 - x^3/48 + x^5/480 ; trunc err < 2e-8 at |x|=0.25
        float x2 = x * x;
        float s = 0.5f + x * (0.25f + x2 * (-2.0833333e-2f + x2 * 2.0833333e-3f));
        return x * s;
    }
    return x / (1.0f + expf(-x));
}

// ---------------------------------------------------------------------------
// Kernel A: precompute tables (blocks 0..207) + zero pool accumulators (208..239)
// grid = 240 blocks x 256 threads
// ---------------------------------------------------------------------------
__global__ void prep_kernel(const float* __restrict__ E_elem,
                            const float* __restrict__ E_aa,
                            const float* __restrict__ E_bb,
                            const float* __restrict__ E_lig,
                            const float* __restrict__ Wd1,
                            const float* __restrict__ bd1) {
    int blk = blockIdx.x;
    int h = threadIdx.x;           // 0..255
    if (blk >= 208) {              // zero pools: 32 blocks * 2048 floats = 65536
        int base = (blk - 208) * 2048;
        #pragma unroll
        for (int r = 0; r < 8; r++) {
            int idx = base + r * 256 + h;
            if (idx < BATCH*H) g_pool_p[idx] = 0.0f;
            else               g_pool_l[idx - BATCH*H] = 0.0f;
        }
        return;
    }
    __shared__ float srow[H];
    float bias = 0.0f;
    float* dst;
    if (blk < 128) {
        srow[h] = E_elem[blk*H + h];
        dst = g_Telem + blk*H;
    } else if (blk < 192) {
        int r = blk - 128;
        int a = r >> 1, bb = r & 1;
        srow[h] = E_aa[a*H + h] + E_bb[bb*H + h];
        bias = bd1[h];
        dst = g_Tab + r*H;
    } else {
        int t = blk - 192;
        srow[h] = E_lig[t*H + h];
        bias = bd1[h];
        dst = g_Tlig + t*H;
    }
    __syncthreads();
    float acc = bias;
    #pragma unroll 8
    for (int k = 0; k < H; k++)
        acc = fmaf(srow[k], Wd1[k*H + h], acc);
    dst[h] = acc;
}

// ---------------------------------------------------------------------------
// Kernel B: per-node silu + pooled accumulation.
// grid = dim3(BATCH, 5): y=0..3 -> protein chunks of 256 nodes, y=4 -> ligand (128 nodes)
// block = 256 threads: tid = slot*64 + fg ; fg handles features [4fg, 4fg+4)
// ---------------------------------------------------------------------------
__global__ void node_kernel(const int* __restrict__ elem,
                            const int* __restrict__ aa,
                            const int* __restrict__ bbone,
                            const int* __restrict__ ltype) {
    int b  = blockIdx.x;
    int cy = blockIdx.y;
    int tid  = threadIdx.x;
    int fg   = tid & 63;
    int slot = tid >> 6;

    __shared__ int sh_e[256];
    __shared__ int sh_ab[256];
    __shared__ float4 sh_acc[256];

    float4 acc = make_float4(0.f, 0.f, 0.f, 0.f);

    if (cy < 4) {
        int base = b*PP + cy*256;
        sh_e[tid]  = elem[base + tid];
        sh_ab[tid] = aa[base + tid]*2 + bbone[base + tid];
        __syncthreads();
        const float4* Te = reinterpret_cast<const float4*>(g_Telem);
        const float4* Ta = reinterpret_cast<const float4*>(g_Tab);
        #pragma unroll 4
        for (int j = slot; j < 256; j += 4) {
            int e  = sh_e[j];
            int ab = sh_ab[j];
            float4 u = Te[e*64 + fg];
            float4 v = Ta[ab*64 + fg];
            acc.x += silu_f(u.x + v.x);
            acc.y += silu_f(u.y + v.y);
            acc.z += silu_f(u.z + v.z);
            acc.w += silu_f(u.w + v.w);
        }
    } else {
        int base = b*LP;
        if (tid < 128) sh_e[tid] = ltype[base + tid];
        __syncthreads();
        const float4* Tl = reinterpret_cast<const float4*>(g_Tlig);
        #pragma unroll 4
        for (int j = slot; j < 128; j += 4) {
            float4 u = Tl[sh_e[j]*64 + fg];
            acc.x += silu_f(u.x);
            acc.y += silu_f(u.y);
            acc.z += silu_f(u.z);
            acc.w += silu_f(u.w);
        }
    }

    sh_acc[tid] = acc;   // tid == slot*64+fg
    __syncthreads();
    if (slot == 0) {
        float4 s0 = sh_acc[fg];
        float4 s1 = sh_acc[64 + fg];
        float4 s2 = sh_acc[128 + fg];
        float4 s3 = sh_acc[192 + fg];
        float4 s;
        s.x = (s0.x + s1.x) + (s2.x + s3.x);
        s.y = (s0.y + s1.y) + (s2.y + s3.y);
        s.z = (s0.z + s1.z) + (s2.z + s3.z);
        s.w = (s0.w + s1.w) + (s2.w + s3.w);
        float* dst = (cy < 4 ? g_pool_p : g_pool_l) + b*H + fg*4;
        atomicAdd(dst + 0, s.x);
        atomicAdd(dst + 1, s.y);
        atomicAdd(dst + 2, s.z);
        atomicAdd(dst + 3, s.w);
    }
}

// ---------------------------------------------------------------------------
// Kernel C: per-batch ligand->protein min distance, contact features.
// grid = BATCH blocks x 256 threads. Thread = (ligand atom, protein half).
// min(sqrt(d2)) = sqrt(min(d2)); one sqrt per ligand atom.
// ---------------------------------------------------------------------------
__global__ void dist_kernel(const float* __restrict__ ppos,
                            const float* __restrict__ lpos) {
    int b = blockIdx.x;
    int tid = threadIdx.x;
    __shared__ float4 sh_p[PP];
    __shared__ float sh_m[256];

    const float* pb = ppos + (size_t)b * PP * 3;
    float* shpf = reinterpret_cast<float*>(sh_p);
    for (int i = tid; i < PP*3; i += 256) {
        int j = i / 3, c = i - j*3;
        shpf[j*4 + c] = pb[i];
    }
    __syncthreads();

    int la   = tid & 127;
    int half = tid >> 7;
    const float* lp = lpos + ((size_t)b*LP + la) * 3;
    float lx = lp[0], ly = lp[1], lz = lp[2];
    float m = 3.4e38f;
    int j0 = half * 512;
    #pragma unroll 4
    for (int j = j0; j < j0 + 512; j++) {
        float4 p = sh_p[j];
        float dx = lx - p.x, dy = ly - p.y, dz = lz - p.z;
        float d2 = fmaf(dx, dx, fmaf(dy, dy, dz*dz));
        m = fminf(m, d2);
    }
    sh_m[tid] = m;
    __syncthreads();
    if (tid < 128) {
        float d = sqrtf(fminf(sh_m[tid], sh_m[tid + 128]));
        sh_m[tid] = d;
    }
    __syncthreads();
    if (tid < 32) {
        float s = 0.0f, mn = 3.4e38f;
        #pragma unroll
        for (int k = tid; k < 128; k += 32) {
            s += sh_m[k];
            mn = fminf(mn, sh_m[k]);
        }
        #pragma unroll
        for (int o = 16; o > 0; o >>= 1) {
            s += __shfl_xor_sync(0xffffffffu, s, o);
            mn = fminf(mn, __shfl_xor_sync(0xffffffffu, mn, o));
        }
        if (tid == 0) {
            g_contact[b*2 + 0] = s * (1.0f / 128.0f);
            g_contact[b*2 + 1] = mn;
        }
    }
}

// ---------------------------------------------------------------------------
// Kernel D: 2 batches per block, grid 64. Weight rows are staged into shared
// memory in 32-row x 256-col tiles via coalesced float4 loads (high MLP),
// then consumed by FMAs from smem. Removes the L2-latency serial-scalar-load
// bottleneck that made the old version 65.7us.
// ---------------------------------------------------------------------------
#define KTILE 32

__global__ void __launch_bounds__(256) final_kernel(
                             const float* __restrict__ Wd2,
                             const float* __restrict__ bd2,
                             const float* __restrict__ Wa1,
                             const float* __restrict__ ba1,
                             const float* __restrict__ Wa2,
                             const float* __restrict__ ba2,
                             float* __restrict__ out) {
    int b0 = blockIdx.x * 2;           // batches b0, b0+1
    int h  = threadIdx.x;              // feature 0..255

    __shared__ float  sW[KTILE * H];   // 32KB weight tile
    __shared__ float4 sA[H];           // {mp0, ml0, mp1, ml1}[k]
    __shared__ float2 sG[2*H];         // {g_b0, g_b1}[k], k<256: gp, k>=256: gl
    __shared__ float2 sRed[H];

    float inv_pp = 1.0f / (float)PP;
    float inv_lp = 1.0f / (float)LP;
    sA[h] = make_float4(g_pool_p[b0*H + h] * inv_pp,
                        g_pool_l[b0*H + h] * inv_lp,
                        g_pool_p[(b0+1)*H + h] * inv_pp,
                        g_pool_l[(b0+1)*H + h] * inv_lp);
    __syncthreads();

    // ---- phase 1: g = pooled @ Wd2 + bd2 (both batches, p & l) ----
    float bd = bd2[h];
    float ap0 = bd, al0 = bd, ap1 = bd, al1 = bd;
    float4* sWv = reinterpret_cast<float4*>(sW);
    #pragma unroll 1
    for (int t = 0; t < H / KTILE; t++) {
        const float4* src = reinterpret_cast<const float4*>(Wd2 + t * KTILE * H);
        #pragma unroll
        for (int i = 0; i < (KTILE*H/4)/256; i++)
            sWv[i*256 + h] = src[i*256 + h];
        __syncthreads();
        #pragma unroll
        for (int kk = 0; kk < KTILE; kk++) {
            float  w = sW[kk*H + h];
            float4 a = sA[t*KTILE + kk];
            ap0 = fmaf(a.x, w, ap0);
            al0 = fmaf(a.y, w, al0);
            ap1 = fmaf(a.z, w, ap1);
            al1 = fmaf(a.w, w, al1);
        }
        __syncthreads();
    }
    sG[h]       = make_float2(ap0, ap1);
    sG[H + h]   = make_float2(al0, al1);
    __syncthreads();

    // ---- phase 2: t = [gp, gl] @ Wa1[0:512] + contact terms + ba1 ----
    float c00 = g_contact[b0*2],     c01 = g_contact[b0*2 + 1];
    float c10 = g_contact[b0*2 + 2], c11 = g_contact[b0*2 + 3];
    float wr0 = Wa1[512*H + h], wr1 = Wa1[513*H + h];
    float ba = ba1[h];
    float t0 = fmaf(c00, wr0, fmaf(c01, wr1, ba));
    float t1 = fmaf(c10, wr0, fmaf(c11, wr1, ba));
    #pragma unroll 1
    for (int t = 0; t < (2*H) / KTILE; t++) {
        const float4* src = reinterpret_cast<const float4*>(Wa1 + t * KTILE * H);
        #pragma unroll
        for (int i = 0; i < (KTILE*H/4)/256; i++)
            sWv[i*256 + h] = src[i*256 + h];
        __syncthreads();
        #pragma unroll
        for (int kk = 0; kk < KTILE; kk++) {
            float  w = sW[kk*H + h];
            float2 g = sG[t*KTILE + kk];
            t0 = fmaf(g.x, w, t0);
            t1 = fmaf(g.y, w, t1);
        }
        __syncthreads();
    }

    // ---- phase 3: silu, dot with Wa2, reduce over h ----
    float wa2 = Wa2[h];
    float v0 = silu_f(t0) * wa2;
    float v1 = silu_f(t1) * wa2;
    sRed[h] = make_float2(v0, v1);
    __syncthreads();
    for (int off = 128; off > 0; off >>= 1) {
        if (h < off) {
            float2 a = sRed[h], b = sRed[h + off];
            sRed[h] = make_float2(a.x + b.x, a.y + b.y);
        }
        __syncthreads();
    }
    if (h == 0) {
        float bb = ba2[0];
        out[b0]     = sRed[0].x + bb;
        out[b0 + 1] = sRed[0].y + bb;
    }
}

// ---------------------------------------------------------------------------
extern "C" void kernel_launch(void* const* d_in, const int* in_sizes, int n_in,
                              void* d_out, int out_size) {
    const float* protein_pos = (const float*)d_in[0];
    const float* ligand_pos  = (const float*)d_in[1];
    const int*   p_elem      = (const int*)d_in[2];
    const int*   p_aa        = (const int*)d_in[3];
    const int*   p_bb        = (const int*)d_in[4];
    const int*   l_type      = (const int*)d_in[5];
    // d_in[6] protein_batch, d_in[7] ligand_batch: contiguous repeat(arange(B)) -> implicit
    const float* E_elem = (const float*)d_in[8];
    const float* E_aa   = (const float*)d_in[9];
    const float* E_bb   = (const float*)d_in[10];
    const float* E_lig  = (const float*)d_in[11];
    const float* Wd1    = (const float*)d_in[12];
    const float* bd1    = (const float*)d_in[13];
    const float* Wd2    = (const float*)d_in[14];
    const float* bd2    = (const float*)d_in[15];
    const float* Wa1    = (const float*)d_in[16];
    const float* ba1    = (const float*)d_in[17];
    const float* Wa2    = (const float*)d_in[18];
    const float* ba2    = (const float*)d_in[19];
    float* out = (float*)d_out;

    prep_kernel<<<240, 256>>>(E_elem, E_aa, E_bb, E_lig, Wd1, bd1);
    dist_kernel<<<BATCH, 256>>>(protein_pos, ligand_pos);
    node_kernel<<<dim3(BATCH, 5), 256>>>(p_elem, p_aa, p_bb, l_type);
    final_kernel<<<64, 256>>>(Wd2, bd2, Wa1, ba1, Wa2, ba2, out);
}

// round 4
// speedup vs baseline: 1.1600x; 1.0538x over previous
#include <cuda_runtime.h>
#include <math.h>

// Problem constants (fixed by setup_inputs)
#define BATCH 128
#define PP 1024
#define LP 128
#define H 256
#define NP (BATCH*PP)
#define NL (BATCH*LP)

// Scratch (device globals: no allocation allowed)
__device__ float g_Telem[128*H];   // E_elem @ Wd1
__device__ float g_Tab[64*H];      // (E_aa + E_bb) @ Wd1 + bd1, indexed by a*2+bb
__device__ float g_Tlig[16*H];     // E_lig @ Wd1 + bd1
__device__ float g_pool_p[BATCH*H];
__device__ float g_pool_l[BATCH*H];
__device__ float g_contact[BATCH*2];
__device__ float g_U[512*H];       // rows 0..255: Wd2@Wa1_p ; rows 256..511: Wd2@Wa1_l
__device__ float g_beff[H];        // ba1 + bd2@(Wa1_p + Wa1_l)

__device__ __forceinline__ float silu_f(float x) {
    float ax = fabsf(x);
    if (ax < 0.25f) {
        // sigmoid(x) = 1/2 + x/4 - x^3/48 + x^5/480 ; trunc err < 2e-8 at |x|=0.25
        float x2 = x * x;
        float s = 0.5f + x * (0.25f + x2 * (-2.0833333e-2f + x2 * 2.0833333e-3f));
        return x * s;
    }
    return x / (1.0f + expf(-x));
}

// ---------------------------------------------------------------------------
// prep_all: one wave of 148 blocks x 256 threads.
//  blocks [0,52)   : node tables = [208 x 256] @ Wd1 tiled GEMM (13 row-slices x 4 h-slices)
//  blocks [52,116) : U = Wd2 @ Wa1[0:512] tiled GEMM (16 i-slices x 4 h-slices) + b_eff
//  blocks [116,148): zero g_pool_p / g_pool_l ; block 116 zeroes d_out[0:128]
// ---------------------------------------------------------------------------
__global__ void __launch_bounds__(256) prep_all(
                          const float* __restrict__ E_elem,
                          const float* __restrict__ E_aa,
                          const float* __restrict__ E_bb,
                          const float* __restrict__ E_lig,
                          const float* __restrict__ Wd1,
                          const float* __restrict__ bd1,
                          const float* __restrict__ Wd2,
                          const float* __restrict__ bd2,
                          const float* __restrict__ Wa1,
                          const float* __restrict__ ba1,
                          float* __restrict__ out) {
    int blk = blockIdx.x;
    int tid = threadIdx.x;

    if (blk >= 116) {   // ---- zero blocks ----
        int base = (blk - 116) * 2048;
        #pragma unroll
        for (int r = 0; r < 8; r++) {
            int idx = base + r * 256 + tid;
            if (idx < BATCH*H) g_pool_p[idx] = 0.0f;
            else               g_pool_l[idx - BATCH*H] = 0.0f;
        }
        if (blk == 116 && tid < BATCH) out[tid] = 0.0f;
        return;
    }

    int hh   = tid & 63;
    int slot = tid >> 6;

    if (blk < 52) {     // ---- table blocks ----
        int rs  = blk % 13;          // row-slice: rows [rs*16, rs*16+16) of 208
        int h_s = blk / 13;          // h-slice: cols [h_s*64, +64)
        int h   = h_s * 64 + hh;

        __shared__ float sSrc[16*256];   // 16KB source rows
        __shared__ float sB[64*64];      // 16KB Wd1 tile
        __shared__ float sBd1[64];

        // stage source rows (float4, warp-uniform branch)
        {
            float4* sv = reinterpret_cast<float4*>(sSrc);
            #pragma unroll
            for (int it = 0; it < 4; it++) {
                int idx4 = tid + it * 256;        // < 1024
                int rl = idx4 >> 6, c4 = idx4 & 63;
                int r = rs * 16 + rl;
                float4 v;
                if (r < 128) {
                    v = reinterpret_cast<const float4*>(E_elem + r*256)[c4];
                } else if (r < 192) {
                    int q = r - 128;
                    float4 a = reinterpret_cast<const float4*>(E_aa + (q>>1)*256)[c4];
                    float4 b = reinterpret_cast<const float4*>(E_bb + (q&1)*256)[c4];
                    v = make_float4(a.x+b.x, a.y+b.y, a.z+b.z, a.w+b.w);
                } else {
                    v = reinterpret_cast<const float4*>(E_lig + (r-192)*256)[c4];
                }
                sv[idx4] = v;
            }
        }
        if (tid < 64) sBd1[tid] = bd1[h_s*64 + tid];
        __syncthreads();

        float acc[4] = {0.f, 0.f, 0.f, 0.f};
        float4* sBv = reinterpret_cast<float4*>(sB);
        for (int t = 0; t < 4; t++) {
            #pragma unroll
            for (int it = 0; it < 4; it++) {
                int idx4 = tid + it * 256;        // 64 rows x 16 float4
                int kr = idx4 >> 4, c4 = idx4 & 15;
                sBv[idx4] = reinterpret_cast<const float4*>(Wd1 + (t*64+kr)*256 + h_s*64)[c4];
            }
            __syncthreads();
            #pragma unroll 8
            for (int kk = 0; kk < 64; kk++) {
                float b = sB[kk*64 + hh];
                int k = t*64 + kk;
                #pragma unroll
                for (int r = 0; r < 4; r++)
                    acc[r] = fmaf(sSrc[(slot*4+r)*256 + k], b, acc[r]);
            }
            __syncthreads();
        }
        #pragma unroll
        for (int r = 0; r < 4; r++) {
            int gr = rs*16 + slot*4 + r;
            float v = acc[r] + (gr >= 128 ? sBd1[hh] : 0.0f);
            if (gr < 128)      g_Telem[gr*256 + h] = v;
            else if (gr < 192) g_Tab[(gr-128)*256 + h] = v;
            else               g_Tlig[(gr-192)*256 + h] = v;
        }
        return;
    }

    // ---- U blocks ----
    {
        int u   = blk - 52;
        int i_s = u % 16;            // i rows [i_s*16, +16)
        int h_s = u / 16;            // h cols [h_s*64, +64)
        int h   = h_s * 64 + hh;

        __shared__ float sWd2[16*256];   // 16KB
        __shared__ float sB[64*64];      // 16KB Wa1 tile
        __shared__ float sBd2[256];

        {
            float4* sv = reinterpret_cast<float4*>(sWd2);
            #pragma unroll
            for (int it = 0; it < 4; it++) {
                int idx4 = tid + it * 256;
                int rl = idx4 >> 6, c4 = idx4 & 63;
                sv[idx4] = reinterpret_cast<const float4*>(Wd2 + (i_s*16+rl)*256)[c4];
            }
        }
        if (i_s == 0) sBd2[tid] = bd2[tid];
        __syncthreads();

        float accp[4] = {0.f,0.f,0.f,0.f};
        float accl[4] = {0.f,0.f,0.f,0.f};
        float acc_be = 0.0f;
        bool do_be = (i_s == 0 && slot == 0);

        float4* sBv = reinterpret_cast<float4*>(sB);
        for (int t = 0; t < 8; t++) {
            #pragma unroll
            for (int it = 0; it < 4; it++) {
                int idx4 = tid + it * 256;
                int kr = idx4 >> 4, c4 = idx4 & 15;
                sBv[idx4] = reinterpret_cast<const float4*>(Wa1 + (t*64+kr)*256 + h_s*64)[c4];
            }
            __syncthreads();
            if (t < 4) {
                #pragma unroll 8
                for (int kk = 0; kk < 64; kk++) {
                    float b = sB[kk*64 + hh];
                    int k = t*64 + kk;
                    #pragma unroll
                    for (int r = 0; r < 4; r++)
                        accp[r] = fmaf(sWd2[(slot*4+r)*256 + k], b, accp[r]);
                    if (do_be) acc_be = fmaf(sBd2[k], b, acc_be);
                }
            } else {
                #pragma unroll 8
                for (int kk = 0; kk < 64; kk++) {
                    float b = sB[kk*64 + hh];
                    int k = (t-4)*64 + kk;
                    #pragma unroll
                    for (int r = 0; r < 4; r++)
                        accl[r] = fmaf(sWd2[(slot*4+r)*256 + k], b, accl[r]);
                    if (do_be) acc_be = fmaf(sBd2[k], b, acc_be);
                }
            }
            __syncthreads();
        }
        #pragma unroll
        for (int r = 0; r < 4; r++) {
            int i = i_s*16 + slot*4 + r;
            g_U[i*256 + h]        = accp[r];
            g_U[(256+i)*256 + h]  = accl[r];
        }
        if (do_be) g_beff[h] = ba1[h] + acc_be;
    }
}

// ---------------------------------------------------------------------------
// node_kernel (unchanged): per-node silu + pooled accumulation.
// ---------------------------------------------------------------------------
__global__ void node_kernel(const int* __restrict__ elem,
                            const int* __restrict__ aa,
                            const int* __restrict__ bbone,
                            const int* __restrict__ ltype) {
    int b  = blockIdx.x;
    int cy = blockIdx.y;
    int tid  = threadIdx.x;
    int fg   = tid & 63;
    int slot = tid >> 6;

    __shared__ int sh_e[256];
    __shared__ int sh_ab[256];
    __shared__ float4 sh_acc[256];

    float4 acc = make_float4(0.f, 0.f, 0.f, 0.f);

    if (cy < 4) {
        int base = b*PP + cy*256;
        sh_e[tid]  = elem[base + tid];
        sh_ab[tid] = aa[base + tid]*2 + bbone[base + tid];
        __syncthreads();
        const float4* Te = reinterpret_cast<const float4*>(g_Telem);
        const float4* Ta = reinterpret_cast<const float4*>(g_Tab);
        #pragma unroll 4
        for (int j = slot; j < 256; j += 4) {
            int e  = sh_e[j];
            int ab = sh_ab[j];
            float4 u = Te[e*64 + fg];
            float4 v = Ta[ab*64 + fg];
            acc.x += silu_f(u.x + v.x);
            acc.y += silu_f(u.y + v.y);
            acc.z += silu_f(u.z + v.z);
            acc.w += silu_f(u.w + v.w);
        }
    } else {
        int base = b*LP;
        if (tid < 128) sh_e[tid] = ltype[base + tid];
        __syncthreads();
        const float4* Tl = reinterpret_cast<const float4*>(g_Tlig);
        #pragma unroll 4
        for (int j = slot; j < 128; j += 4) {
            float4 u = Tl[sh_e[j]*64 + fg];
            acc.x += silu_f(u.x);
            acc.y += silu_f(u.y);
            acc.z += silu_f(u.z);
            acc.w += silu_f(u.w);
        }
    }

    sh_acc[tid] = acc;
    __syncthreads();
    if (slot == 0) {
        float4 s0 = sh_acc[fg];
        float4 s1 = sh_acc[64 + fg];
        float4 s2 = sh_acc[128 + fg];
        float4 s3 = sh_acc[192 + fg];
        float4 s;
        s.x = (s0.x + s1.x) + (s2.x + s3.x);
        s.y = (s0.y + s1.y) + (s2.y + s3.y);
        s.z = (s0.z + s1.z) + (s2.z + s3.z);
        s.w = (s0.w + s1.w) + (s2.w + s3.w);
        float* dst = (cy < 4 ? g_pool_p : g_pool_l) + b*H + fg*4;
        atomicAdd(dst + 0, s.x);
        atomicAdd(dst + 1, s.y);
        atomicAdd(dst + 2, s.z);
        atomicAdd(dst + 3, s.w);
    }
}

// ---------------------------------------------------------------------------
// dist_kernel (unchanged): per-batch ligand->protein min distance.
// ---------------------------------------------------------------------------
__global__ void dist_kernel(const float* __restrict__ ppos,
                            const float* __restrict__ lpos) {
    int b = blockIdx.x;
    int tid = threadIdx.x;
    __shared__ float4 sh_p[PP];
    __shared__ float sh_m[256];

    const float* pb = ppos + (size_t)b * PP * 3;
    float* shpf = reinterpret_cast<float*>(sh_p);
    for (int i = tid; i < PP*3; i += 256) {
        int j = i / 3, c = i - j*3;
        shpf[j*4 + c] = pb[i];
    }
    __syncthreads();

    int la   = tid & 127;
    int half = tid >> 7;
    const float* lp = lpos + ((size_t)b*LP + la) * 3;
    float lx = lp[0], ly = lp[1], lz = lp[2];
    float m = 3.4e38f;
    int j0 = half * 512;
    #pragma unroll 4
    for (int j = j0; j < j0 + 512; j++) {
        float4 p = sh_p[j];
        float dx = lx - p.x, dy = ly - p.y, dz = lz - p.z;
        float d2 = fmaf(dx, dx, fmaf(dy, dy, dz*dz));
        m = fminf(m, d2);
    }
    sh_m[tid] = m;
    __syncthreads();
    if (tid < 128) {
        float d = sqrtf(fminf(sh_m[tid], sh_m[tid + 128]));
        sh_m[tid] = d;
    }
    __syncthreads();
    if (tid < 32) {
        float s = 0.0f, mn = 3.4e38f;
        #pragma unroll
        for (int k = tid; k < 128; k += 32) {
            s += sh_m[k];
            mn = fminf(mn, sh_m[k]);
        }
        #pragma unroll
        for (int o = 16; o > 0; o >>= 1) {
            s += __shfl_xor_sync(0xffffffffu, s, o);
            mn = fminf(mn, __shfl_xor_sync(0xffffffffu, mn, o));
        }
        if (tid == 0) {
            g_contact[b*2 + 0] = s * (1.0f / 128.0f);
            g_contact[b*2 + 1] = mn;
        }
    }
}

// ---------------------------------------------------------------------------
// final_kernel: T = A @ U with A=[128 x 512] pooled means, single pass.
// grid 64 = 16 batch-slices (8 batches) x 4 h-slices (64 h).
// Each block owns full K for its h-slice -> silu + Wa2 dot locally,
// warp-shfl reduce, atomicAdd into pre-zeroed d_out.
// ---------------------------------------------------------------------------
__global__ void __launch_bounds__(256) final_kernel(
                             const float* __restrict__ Wa1,
                             const float* __restrict__ Wa2,
                             const float* __restrict__ ba2,
                             float* __restrict__ out) {
    int bs  = blockIdx.x & 15;     // batch slice
    int h_s = blockIdx.x >> 4;     // h slice
    int tid = threadIdx.x;
    int hh   = tid & 63;
    int slot = tid >> 6;
    int h = h_s * 64 + hh;

    __shared__ float sA[8*512];    // 16KB pooled rows (scaled)
    __shared__ float sU[64*64];    // 16KB U tile

    // stage A: sA[b_local][k] ; k<256: mean_p, k>=256: mean_l
    {
        float4* sv = reinterpret_cast<float4*>(sA);
        #pragma unroll
        for (int it = 0; it < 4; it++) {
            int idx4 = tid + it * 256;       // < 1024 ; 8 rows x 128 float4
            int bl = idx4 >> 7, q = idx4 & 127;
            int b = bs*8 + bl;
            float4 v; float sc;
            if (q < 64) {
                v = reinterpret_cast<const float4*>(g_pool_p + b*256)[q];
                sc = 1.0f / (float)PP;
            } else {
                v = reinterpret_cast<const float4*>(g_pool_l + b*256)[q - 64];
                sc = 1.0f / (float)LP;
            }
            sv[idx4] = make_float4(v.x*sc, v.y*sc, v.z*sc, v.w*sc);
        }
    }
    __syncthreads();

    float acc0 = 0.f, acc1 = 0.f;
    const float* a0p = sA + (slot*2 + 0)*512;
    const float* a1p = sA + (slot*2 + 1)*512;
    float4* sUv = reinterpret_cast<float4*>(sU);
    for (int t = 0; t < 8; t++) {
        #pragma unroll
        for (int it = 0; it < 4; it++) {
            int idx4 = tid + it * 256;
            int kr = idx4 >> 4, c4 = idx4 & 15;
            sUv[idx4] = reinterpret_cast<const float4*>(g_U + (t*64+kr)*256 + h_s*64)[c4];
        }
        __syncthreads();
        #pragma unroll 8
        for (int kk = 0; kk < 64; kk++) {
            float u = sU[kk*64 + hh];
            int k = t*64 + kk;
            acc0 = fmaf(a0p[k], u, acc0);
            acc1 = fmaf(a1p[k], u, acc1);
        }
        __syncthreads();
    }

    // epilogue: add b_eff + contact terms, silu, * Wa2, reduce
    int b0 = bs*8 + slot*2;
    int b1 = b0 + 1;
    float be  = g_beff[h];
    float wc0 = Wa1[512*256 + h];
    float wc1 = Wa1[513*256 + h];
    float wa2 = Wa2[h];
    float c00 = g_contact[b0*2], c01 = g_contact[b0*2 + 1];
    float c10 = g_contact[b1*2], c11 = g_contact[b1*2 + 1];

    float t0 = acc0 + be + c00*wc0 + c01*wc1;
    float t1 = acc1 + be + c10*wc0 + c11*wc1;
    float v0 = silu_f(t0) * wa2;
    float v1 = silu_f(t1) * wa2;

    #pragma unroll
    for (int o = 16; o > 0; o >>= 1) {
        v0 += __shfl_xor_sync(0xffffffffu, v0, o);
        v1 += __shfl_xor_sync(0xffffffffu, v1, o);
    }
    int lane = tid & 31;
    if (lane == 0) {
        if (h_s == 0 && (tid & 32) == 0) {   // exactly one warp per batch adds ba2
            float bb = ba2[0];
            v0 += bb; v1 += bb;
        }
        atomicAdd(out + b0, v0);
        atomicAdd(out + b1, v1);
    }
}

// ---------------------------------------------------------------------------
extern "C" void kernel_launch(void* const* d_in, const int* in_sizes, int n_in,
                              void* d_out, int out_size) {
    const float* protein_pos = (const float*)d_in[0];
    const float* ligand_pos  = (const float*)d_in[1];
    const int*   p_elem      = (const int*)d_in[2];
    const int*   p_aa        = (const int*)d_in[3];
    const int*   p_bb        = (const int*)d_in[4];
    const int*   l_type      = (const int*)d_in[5];
    // d_in[6] protein_batch, d_in[7] ligand_batch: contiguous repeat(arange(B)) -> implicit
    const float* E_elem = (const float*)d_in[8];
    const float* E_aa   = (const float*)d_in[9];
    const float* E_bb   = (const float*)d_in[10];
    const float* E_lig  = (const float*)d_in[11];
    const float* Wd1    = (const float*)d_in[12];
    const float* bd1    = (const float*)d_in[13];
    const float* Wd2    = (const float*)d_in[14];
    const float* bd2    = (const float*)d_in[15];
    const float* Wa1    = (const float*)d_in[16];
    const float* ba1    = (const float*)d_in[17];
    const float* Wa2    = (const float*)d_in[18];
    const float* ba2    = (const float*)d_in[19];
    float* out = (float*)d_out;

    prep_all<<<148, 256>>>(E_elem, E_aa, E_bb, E_lig, Wd1, bd1,
                           Wd2, bd2, Wa1, ba1, out);
    dist_kernel<<<BATCH, 256>>>(protein_pos, ligand_pos);
    node_kernel<<<dim3(BATCH, 5), 256>>>(p_elem, p_aa, p_bb, l_type);
    final_kernel<<<64, 256>>>(Wa1, Wa2, ba2, out);
}